// round 16
// baseline (speedup 1.0000x reference)
#include <cuda_runtime.h>
#include <cuda_fp16.h>
#include <math.h>
#include <stdint.h>

#define NROWS 65536
#define DIMS  64
#define KCODE 1024
#define BM    256           // rows per block (2 groups of 128)
#define THREADS 256
#define NCHUNK 32           // 32 chunks of 32 codes
#define CHW    32
#define NBLK   (NROWS/BM)   // 256 row-blocks
#define GRID   296          // all-resident (148 SMs x occ 2); work-stealing
#define NPREP  260

// output layout (floats): [loss(1) | quantized(4194304) | perplexity(1) | encodings(67108864)]
#define Q_OFF    1
#define Q_SIZE   4194304
#define P_OFF    (Q_OFF + Q_SIZE)
#define ENC_OFF  (P_OFF + 1)

#define LDB   72            // padded fp16 row: 144B (conflict-free ldmatrix)
#define LDBB  144
#define IMGB  (KCODE * LDBB)      // 147456 per codebook image
#define CHB   4608                // bytes per image per 32-code chunk
#define AIMG  (BM * LDBB)         // 36864 per A image
#define ESC   256.0f
#define NEG1S (-1.0f/256.0f)

// smem byte offsets
#define A_OFF    0                    // 2 images x 256 x 144 = 73728
#define B_OFF    73728                // 2 bufs x 9216
#define BCHUNKB  9216
#define HE2_OFF  92160                // 1024 f32 (0.5*e2)
#define X2_OFF   96256                // 256 f32
#define RMIN_OFF 97280                // 256 f32
#define RIDX_OFF 98304                // 256 i32
#define BLK_OFF  99328
#define SMEM_BYTES 99456              // x2 = 198912 <= 228KB

__device__ __half g_cbs[2 * KCODE * LDB];  // 2 padded split images (scaled x256)
__device__ float  g_he2[KCODE];            // 0.5 * ||e||^2
__device__ int    g_counts[KCODE];
__device__ double g_loss_sum;
__device__ int    g_blk;
__device__ int    g_prep_done;
__device__ int    g_done;

__device__ __forceinline__ uint32_t smem_u32(const void* p) {
    uint32_t a;
    asm("{ .reg .u64 t; cvta.to.shared.u64 t, %1; cvt.u32.u64 %0, t; }" : "=r"(a) : "l"(p));
    return a;
}
#define LDSM_X4(r0, r1, r2, r3, addr) \
    asm volatile("ldmatrix.sync.aligned.m8n8.x4.shared.b16 {%0,%1,%2,%3}, [%4];" \
                 : "=r"(r0), "=r"(r1), "=r"(r2), "=r"(r3) : "r"(addr))
#define MMA_F16(c0, c1, c2, c3, a0, a1, a2, a3, b0, b1) \
    asm volatile("mma.sync.aligned.m16n8k16.row.col.f32.f16.f16.f32 " \
                 "{%0,%1,%2,%3}, {%4,%5,%6,%7}, {%8,%9}, {%0,%1,%2,%3};" \
                 : "+f"(c0), "+f"(c1), "+f"(c2), "+f"(c3) \
                 : "r"(a0), "r"(a1), "r"(a2), "r"(a3), "r"(b0), "r"(b1))
#define CPA16(dst, src) \
    asm volatile("cp.async.cg.shared.global [%0], [%1], 16;" \
                 :: "r"((uint32_t)(dst)), "l"((unsigned long long)(src)) : "memory")
#define CPA_COMMIT() asm volatile("cp.async.commit_group;" ::: "memory")
#define CPA_WAIT0()  asm volatile("cp.async.wait_group 0;" ::: "memory")

// ---------------- single fused persistent kernel ----------------
__global__ __launch_bounds__(THREADS, 2)
void vq_kernel(const float* __restrict__ x,
               const float* __restrict__ cb,
               float* __restrict__ out) {
    extern __shared__ char smem[];
    const uint32_t su = smem_u32(smem);
    float* he2s = (float*)(smem + HE2_OFF);
    float* x2s  = (float*)(smem + X2_OFF);
    float* rmin = (float*)(smem + RMIN_OFF);
    int*   ridx = (int*)(smem + RIDX_OFF);
    int*   sblk = (int*)(smem + BLK_OFF);
    int*   slast = (int*)(smem + BLK_OFF + 4);

    const int tid  = threadIdx.x;
    const int wid  = tid >> 5;
    const int lane = tid & 31;
    const int bid  = blockIdx.x;

    // ================= phase 0: distributed codebook prep =================
    if (bid < 256) {
        int idx = bid * 256 + tid;          // one element per thread
        int k = idx >> 6, c = idx & 63;
        float v = cb[idx];
        float vs = v * ESC;
        __half h = __float2half_rn(vs);
        float r1 = vs - __half2float(h);
        __half l = __float2half_rn(r1);
        g_cbs[k * LDB + c] = h;
        g_cbs[KCODE * LDB + k * LDB + c] = l;
        __threadfence();
        __syncthreads();
        if (tid == 0) atomicAdd(&g_prep_done, 1);
    } else if (bid < NPREP) {
        int k = (bid - 256) * 256 + tid;    // one code per thread
        float e2 = 0.f;
        #pragma unroll 8
        for (int c = 0; c < DIMS; c++) {
            float v = cb[k * DIMS + c];
            e2 = fmaf(v, v, e2);
        }
        g_he2[k] = 0.5f * e2;
        __threadfence();
        __syncthreads();
        if (tid == 0) atomicAdd(&g_prep_done, 1);
    }
    if (tid == 0) {
        while (atomicAdd(&g_prep_done, 0) < NPREP) __nanosleep(64);
    }
    __syncthreads();
    __threadfence();

    #pragma unroll
    for (int i = tid; i < KCODE; i += THREADS) he2s[i] = g_he2[i];

    // cp.async slot map: 576 x 16B lines/chunk; slots 0,1 all threads, slot 2 iff tid<64
    const unsigned long long gb = (unsigned long long)__cvta_generic_to_global(g_cbs);
    unsigned long long cpa_src[3];
    uint32_t cpa_dst[3];
    const bool has3 = (tid < 64);
    #pragma unroll
    for (int u = 0; u < 3; u++) {
        int i = tid + u * 256;
        int q = i / 288, r = i % 288;
        cpa_dst[u] = (uint32_t)(q * CHB + r * 16);
        cpa_src[u] = gb + (unsigned long long)q * IMGB + (unsigned long long)r * 16;
    }

    const int bofs4 = (lane & 7) * LDBB + ((lane >> 3) & 1) * 16 + (lane >> 4) * 32;

    // ================= phase 1: persistent work-stealing main loop =================
    while (true) {
        __syncthreads();
        if (tid == 0) *sblk = atomicAdd(&g_blk, 1);
        __syncthreads();
        const int blk = *sblk;
        if (blk >= NBLK) break;

        const int n0  = blk * BM;
        const int b   = n0 >> 10;
        const int hw0 = n0 & 1023;           // multiple of 256; no image straddle
        const float* xb = x + (size_t)b * 65536 + hw0;

        // prefetch B chunk 0
        {
            uint32_t d0 = su + B_OFF;
            CPA16(d0 + cpa_dst[0], cpa_src[0]);
            CPA16(d0 + cpa_dst[1], cpa_src[1]);
            if (has3) CPA16(d0 + cpa_dst[2], cpa_src[2]);
            CPA_COMMIT();
        }

        // A setup: one row per thread (256 rows)
        {
            int r = tid;
            float x2 = 0.f;
            #pragma unroll 8
            for (int c = 0; c < DIMS; c++) {
                float v = xb[c * 1024 + r];
                x2 = fmaf(v, v, x2);
                __half h = __float2half_rn(v);
                float rr1 = v - __half2float(h);
                __half l = __float2half_rn(rr1);
                *(__half*)(smem + A_OFF + r * LDBB + c * 2) = h;
                *(__half*)(smem + A_OFF + AIMG + r * LDBB + c * 2) = l;
            }
            x2s[r] = x2;
        }
        __syncthreads();

        // A fragments: 2 row-groups x 2 images x 4 k-steps (resident)
        uint32_t af[2][2][4][4];
        {
            int kh = (lane >> 4) & 1;
            #pragma unroll
            for (int g = 0; g < 2; g++) {
                int row = g * 128 + wid * 16 + (lane & 15);
                #pragma unroll
                for (int q = 0; q < 2; q++)
                    #pragma unroll
                    for (int ks = 0; ks < 4; ks++) {
                        uint32_t a = su + A_OFF + q * AIMG + row * LDBB + ks * 32 + kh * 16;
                        LDSM_X4(af[g][q][ks][0], af[g][q][ks][1],
                                af[g][q][ks][2], af[g][q][ks][3], a);
                    }
            }
        }

        float best0[2] = {3.4e38f, 3.4e38f}, best1[2] = {3.4e38f, 3.4e38f};
        int   bidx0[2] = {0, 0},             bidx1[2] = {0, 0};

        float* encb = out + ENC_OFF + (size_t)n0 * KCODE;
        float4* enc4 = (float4*)(encb + 2);
        if (tid == 0) *(float2*)encb = make_float2(0.f, 0.f);
        if (tid == 1) *(float2*)(encb + (size_t)BM * KCODE - 2) = make_float2(0.f, 0.f);

        for (int nt = 0; nt < NCHUNK; nt++) {
            CPA_WAIT0();
            __syncthreads();
            if (nt + 1 < NCHUNK) {
                uint32_t d0 = su + B_OFF + ((nt + 1) & 1) * BCHUNKB;
                unsigned long long so = (unsigned long long)(nt + 1) * CHB;
                CPA16(d0 + cpa_dst[0], cpa_src[0] + so);
                CPA16(d0 + cpa_dst[1], cpa_src[1] + so);
                if (has3) CPA16(d0 + cpa_dst[2], cpa_src[2] + so);
                CPA_COMMIT();
            }
            const uint32_t bufo = su + B_OFF + (nt & 1) * BCHUNKB;

            float acc[2][4][4];   // [group][t][j]
            #pragma unroll
            for (int g = 0; g < 2; g++)
                #pragma unroll
                for (int t = 0; t < 4; t++)
                    #pragma unroll
                    for (int j = 0; j < 4; j++) acc[g][t][j] = 0.f;

            #pragma unroll
            for (int kp = 0; kp < 2; kp++) {        // ks pairs {0,1}, {2,3}
                const int k0 = kp * 2, k1 = kp * 2 + 1;
                #pragma unroll
                for (int t = 0; t < 4; t++) {
                    const uint32_t tb = bufo + t * 8 * LDBB + kp * 64 + bofs4;
                    uint32_t bh[4], bl[4];
                    LDSM_X4(bh[0], bh[1], bh[2], bh[3], tb);
                    LDSM_X4(bl[0], bl[1], bl[2], bl[3], tb + CHB);
                    // per-acc order: hh@k0, hl@k0, lh@k0, hh@k1, hl@k1, lh@k1
                    #pragma unroll
                    for (int g = 0; g < 2; g++)
                        MMA_F16(acc[g][t][0],acc[g][t][1],acc[g][t][2],acc[g][t][3],
                                af[g][0][k0][0],af[g][0][k0][1],af[g][0][k0][2],af[g][0][k0][3],
                                bh[0],bh[1]);
                    #pragma unroll
                    for (int g = 0; g < 2; g++)
                        MMA_F16(acc[g][t][0],acc[g][t][1],acc[g][t][2],acc[g][t][3],
                                af[g][0][k0][0],af[g][0][k0][1],af[g][0][k0][2],af[g][0][k0][3],
                                bl[0],bl[1]);
                    #pragma unroll
                    for (int g = 0; g < 2; g++)
                        MMA_F16(acc[g][t][0],acc[g][t][1],acc[g][t][2],acc[g][t][3],
                                af[g][1][k0][0],af[g][1][k0][1],af[g][1][k0][2],af[g][1][k0][3],
                                bh[0],bh[1]);
                    #pragma unroll
                    for (int g = 0; g < 2; g++)
                        MMA_F16(acc[g][t][0],acc[g][t][1],acc[g][t][2],acc[g][t][3],
                                af[g][0][k1][0],af[g][0][k1][1],af[g][0][k1][2],af[g][0][k1][3],
                                bh[2],bh[3]);
                    #pragma unroll
                    for (int g = 0; g < 2; g++)
                        MMA_F16(acc[g][t][0],acc[g][t][1],acc[g][t][2],acc[g][t][3],
                                af[g][0][k1][0],af[g][0][k1][1],af[g][0][k1][2],af[g][0][k1][3],
                                bl[2],bl[3]);
                    #pragma unroll
                    for (int g = 0; g < 2; g++)
                        MMA_F16(acc[g][t][0],acc[g][t][1],acc[g][t][2],acc[g][t][3],
                                af[g][1][k1][0],af[g][1][k1][1],af[g][1][k1][2],af[g][1][k1][3],
                                bh[2],bh[3]);
                }
            }

            // epilogue: d_cmp = he2 - dot/256 (monotone in true distance)
            const int cb0 = nt * CHW + (lane & 3) * 2;
            #pragma unroll
            for (int g = 0; g < 2; g++) {
                float d0[8], d1[8];
                #pragma unroll
                for (int t = 0; t < 4; t++) {
                    float ha = he2s[cb0 + t * 8], hb = he2s[cb0 + t * 8 + 1];
                    d0[2*t]   = fmaf(NEG1S, acc[g][t][0], ha);
                    d0[2*t+1] = fmaf(NEG1S, acc[g][t][1], hb);
                    d1[2*t]   = fmaf(NEG1S, acc[g][t][2], ha);
                    d1[2*t+1] = fmaf(NEG1S, acc[g][t][3], hb);
                }
                float m0 = fminf(fminf(fminf(d0[0],d0[1]), fminf(d0[2],d0[3])),
                                 fminf(fminf(d0[4],d0[5]), fminf(d0[6],d0[7])));
                float m1 = fminf(fminf(fminf(d1[0],d1[1]), fminf(d1[2],d1[3])),
                                 fminf(fminf(d1[4],d1[5]), fminf(d1[6],d1[7])));
                if (m0 < best0[g]) {       // strict < keeps lowest-index semantics
                    best0[g] = m0;
                    #pragma unroll
                    for (int j = 7; j >= 0; j--)
                        if (d0[j] == m0) bidx0[g] = cb0 + (j >> 1) * 8 + (j & 1);
                }
                if (m1 < best1[g]) {
                    best1[g] = m1;
                    #pragma unroll
                    for (int j = 7; j >= 0; j--)
                        if (d1[j] == m1) bidx1[g] = cb0 + (j >> 1) * 8 + (j & 1);
                }
            }

            // interleaved encodings zero-fill (65535 float4 per block)
            #pragma unroll
            for (int u = 0; u < 8; u++) {
                int i = nt * 2048 + u * 256 + tid;
                if (i < 65535) enc4[i] = make_float4(0.f, 0.f, 0.f, 0.f);
            }
        }

        // cross-lane argmin reduce (4 lanes per row), idx tie-break
        #pragma unroll
        for (int g = 0; g < 2; g++) {
            #pragma unroll
            for (int off = 1; off < 4; off <<= 1) {
                float ob = __shfl_xor_sync(0xffffffffu, best0[g], off);
                int   oi = __shfl_xor_sync(0xffffffffu, bidx0[g], off);
                if (ob < best0[g] || (ob == best0[g] && oi < bidx0[g])) { best0[g] = ob; bidx0[g] = oi; }
                ob = __shfl_xor_sync(0xffffffffu, best1[g], off);
                oi = __shfl_xor_sync(0xffffffffu, bidx1[g], off);
                if (ob < best1[g] || (ob == best1[g] && oi < bidx1[g])) { best1[g] = ob; bidx1[g] = oi; }
            }
            if ((lane & 3) == 0) {
                int r0 = g * 128 + wid * 16 + (lane >> 2);
                rmin[r0] = fmaf(2.f, best0[g], x2s[r0]);     ridx[r0] = bidx0[g];
                rmin[r0 + 8] = fmaf(2.f, best1[g], x2s[r0 + 8]); ridx[r0 + 8] = bidx1[g];
            }
        }
        __syncthreads();

        atomicAdd(&g_counts[ridx[tid]], 1);     // 256 rows, one per thread

        if (tid < 32) {
            double s = 0.0;
            #pragma unroll
            for (int k = 0; k < 8; k++) s += (double)rmin[tid + k * 32];
            #pragma unroll
            for (int o = 16; o > 0; o >>= 1)
                s += __shfl_down_sync(0xffffffffu, s, o);
            if (tid == 0) atomicAdd(&g_loss_sum, s);
        }

        // quantized output (NCHW), coalesced over r
        float* qout = out + Q_OFF;
        #pragma unroll
        for (int i = 0; i < (BM * DIMS) / THREADS; i++) {   // 64
            int idx = tid + i * THREADS;
            int c = idx >> 8;
            int r = idx & 255;
            qout[(size_t)b * 65536 + (size_t)c * 1024 + hw0 + r] =
                cb[(size_t)ridx[r] * DIMS + c];
        }

        encb[(size_t)tid * KCODE + ridx[tid]] = 1.0f;
    }

    // ================= phase 2: last CTA finalizes + resets state =================
    __threadfence();
    if (tid == 0) {
        int d = atomicAdd(&g_done, 1);
        *slast = (d == GRID - 1) ? 1 : 0;
    }
    __syncthreads();
    if (*slast) {
        __threadfence();
        float* red = x2s;               // reuse smem scratch
        float acc = 0.f;
        #pragma unroll
        for (int i = 0; i < 4; i++) {
            int k = tid + i * 256;
            int c = g_counts[k];
            g_counts[k] = 0;
            float p = (float)c * (1.f / 65536.f);
            acc += p * logf(p + 1e-10f);
        }
        #pragma unroll
        for (int o = 16; o > 0; o >>= 1)
            acc += __shfl_down_sync(0xffffffffu, acc, o);
        if (lane == 0) red[wid] = acc;
        __syncthreads();
        if (tid == 0) {
            float s = 0.f;
            #pragma unroll
            for (int w = 0; w < 8; w++) s += red[w];
            out[P_OFF] = expf(-s);
            out[0]     = (float)(1.25 * g_loss_sum / 4194304.0);
            g_loss_sum   = 0.0;
            g_blk        = 0;
            g_done       = 0;
            g_prep_done  = 0;
        }
    }
}

extern "C" void kernel_launch(void* const* d_in, const int* in_sizes, int n_in,
                              void* d_out, int out_size) {
    const float* x  = (const float*)d_in[0];
    const float* cb = (const float*)d_in[1];
    float* out = (float*)d_out;

    cudaFuncSetAttribute(vq_kernel,
                         cudaFuncAttributeMaxDynamicSharedMemorySize, SMEM_BYTES);

    vq_kernel<<<GRID, THREADS, SMEM_BYTES>>>(x, cb, out);
}

// round 17
// speedup vs baseline: 1.0262x; 1.0262x over previous
#include <cuda_runtime.h>
#include <cuda_fp16.h>
#include <math.h>
#include <stdint.h>

#define NROWS 65536
#define DIMS  64
#define KCODE 1024
#define BM    256           // rows per block (2 groups of 128)
#define THREADS 256
#define NCHUNK 32           // 32 chunks of 32 codes
#define CHW    32
#define NBLK   (NROWS/BM)   // 256 row-blocks
#define GRID   296          // all-resident (148 SMs x occ 2); work-stealing
#define NPREP  260

// output layout (floats): [loss(1) | quantized(4194304) | perplexity(1) | encodings(67108864)]
#define Q_OFF    1
#define Q_SIZE   4194304
#define P_OFF    (Q_OFF + Q_SIZE)
#define ENC_OFF  (P_OFF + 1)

#define LDB   72            // padded fp16 row: 144B (conflict-free ldmatrix)
#define LDBB  144
#define IMGB  (KCODE * LDBB)      // 147456 per codebook image
#define CHB   4608                // bytes per image per 32-code chunk
#define AIMG  (BM * LDBB)         // 36864 per A image
#define ESC   256.0f
#define NEG1S (-1.0f/256.0f)

// smem byte offsets
#define A_OFF    0                    // 2 images x 256 x 144 = 73728
#define B_OFF    73728                // 2 bufs x 9216
#define BCHUNKB  9216
#define HE2_OFF  92160                // 1024 f32 (0.5*e2)
#define X2_OFF   96256                // 256 f32
#define RMIN_OFF 97280                // 256 f32
#define RIDX_OFF 98304                // 256 i32
#define BLK_OFF  99328
#define SMEM_BYTES 99456              // x2 = 198912 <= 228KB

__device__ __half g_cbs[2 * KCODE * LDB];  // 2 padded split images (scaled x256)
__device__ float  g_he2[KCODE];            // 0.5 * ||e||^2
__device__ int    g_counts[KCODE];
__device__ double g_loss_sum;
__device__ int    g_blk;
__device__ int    g_prep_done;
__device__ int    g_done;

__device__ __forceinline__ uint32_t smem_u32(const void* p) {
    uint32_t a;
    asm("{ .reg .u64 t; cvta.to.shared.u64 t, %1; cvt.u32.u64 %0, t; }" : "=r"(a) : "l"(p));
    return a;
}
#define LDSM_X4(r0, r1, r2, r3, addr) \
    asm volatile("ldmatrix.sync.aligned.m8n8.x4.shared.b16 {%0,%1,%2,%3}, [%4];" \
                 : "=r"(r0), "=r"(r1), "=r"(r2), "=r"(r3) : "r"(addr))
#define MMA_F16(c0, c1, c2, c3, a0, a1, a2, a3, b0, b1) \
    asm volatile("mma.sync.aligned.m16n8k16.row.col.f32.f16.f16.f32 " \
                 "{%0,%1,%2,%3}, {%4,%5,%6,%7}, {%8,%9}, {%0,%1,%2,%3};" \
                 : "+f"(c0), "+f"(c1), "+f"(c2), "+f"(c3) \
                 : "r"(a0), "r"(a1), "r"(a2), "r"(a3), "r"(b0), "r"(b1))
#define CPA16(dst, src) \
    asm volatile("cp.async.cg.shared.global [%0], [%1], 16;" \
                 :: "r"((uint32_t)(dst)), "l"((unsigned long long)(src)) : "memory")
#define CPA_COMMIT() asm volatile("cp.async.commit_group;" ::: "memory")
#define CPA_WAIT0()  asm volatile("cp.async.wait_group 0;" ::: "memory")

// ---------------- single fused persistent kernel ----------------
__global__ __launch_bounds__(THREADS, 2)
void vq_kernel(const float* __restrict__ x,
               const float* __restrict__ cb,
               float* __restrict__ out) {
    extern __shared__ char smem[];
    const uint32_t su = smem_u32(smem);
    float* he2s = (float*)(smem + HE2_OFF);
    float* x2s  = (float*)(smem + X2_OFF);
    float* rmin = (float*)(smem + RMIN_OFF);
    int*   ridx = (int*)(smem + RIDX_OFF);
    int*   sblk = (int*)(smem + BLK_OFF);
    int*   slast = (int*)(smem + BLK_OFF + 4);

    const int tid  = threadIdx.x;
    const int wid  = tid >> 5;
    const int lane = tid & 31;
    const int bid  = blockIdx.x;

    // ================= phase 0: distributed codebook prep =================
    if (bid < 256) {
        int idx = bid * 256 + tid;          // one element per thread
        int k = idx >> 6, c = idx & 63;
        float v = cb[idx];
        float vs = v * ESC;
        __half h = __float2half_rn(vs);
        float r1 = vs - __half2float(h);
        __half l = __float2half_rn(r1);
        g_cbs[k * LDB + c] = h;
        g_cbs[KCODE * LDB + k * LDB + c] = l;
        __threadfence();
        __syncthreads();
        if (tid == 0) atomicAdd(&g_prep_done, 1);
    } else if (bid < NPREP) {
        int k = (bid - 256) * 256 + tid;    // one code per thread
        float e2 = 0.f;
        #pragma unroll 8
        for (int c = 0; c < DIMS; c++) {
            float v = cb[k * DIMS + c];
            e2 = fmaf(v, v, e2);
        }
        g_he2[k] = 0.5f * e2;
        __threadfence();
        __syncthreads();
        if (tid == 0) atomicAdd(&g_prep_done, 1);
    }
    if (tid == 0) {
        while (atomicAdd(&g_prep_done, 0) < NPREP) __nanosleep(64);
    }
    __syncthreads();
    __threadfence();

    #pragma unroll
    for (int i = tid; i < KCODE; i += THREADS) he2s[i] = g_he2[i];

    // cp.async slot map: 576 x 16B lines/chunk; slots 0,1 all threads, slot 2 iff tid<64
    const unsigned long long gb = (unsigned long long)__cvta_generic_to_global(g_cbs);
    unsigned long long cpa_src[3];
    uint32_t cpa_dst[3];
    const bool has3 = (tid < 64);
    #pragma unroll
    for (int u = 0; u < 3; u++) {
        int i = tid + u * 256;
        int q = i / 288, r = i % 288;
        cpa_dst[u] = (uint32_t)(q * CHB + r * 16);
        cpa_src[u] = gb + (unsigned long long)q * IMGB + (unsigned long long)r * 16;
    }

    const int bofs4 = (lane & 7) * LDBB + ((lane >> 3) & 1) * 16 + (lane >> 4) * 32;

    // ================= phase 1: persistent work-stealing main loop =================
    while (true) {
        __syncthreads();
        if (tid == 0) *sblk = atomicAdd(&g_blk, 1);
        __syncthreads();
        const int blk = *sblk;
        if (blk >= NBLK) break;

        const int n0  = blk * BM;
        const int b   = n0 >> 10;
        const int hw0 = n0 & 1023;           // multiple of 256; no image straddle
        const float* xb = x + (size_t)b * 65536 + hw0;

        // prefetch B chunk 0
        {
            uint32_t d0 = su + B_OFF;
            CPA16(d0 + cpa_dst[0], cpa_src[0]);
            CPA16(d0 + cpa_dst[1], cpa_src[1]);
            if (has3) CPA16(d0 + cpa_dst[2], cpa_src[2]);
            CPA_COMMIT();
        }

        // A setup: one row per thread (256 rows)
        {
            int r = tid;
            float x2 = 0.f;
            #pragma unroll 8
            for (int c = 0; c < DIMS; c++) {
                float v = xb[c * 1024 + r];
                x2 = fmaf(v, v, x2);
                __half h = __float2half_rn(v);
                float rr1 = v - __half2float(h);
                __half l = __float2half_rn(rr1);
                *(__half*)(smem + A_OFF + r * LDBB + c * 2) = h;
                *(__half*)(smem + A_OFF + AIMG + r * LDBB + c * 2) = l;
            }
            x2s[r] = x2;
        }
        __syncthreads();

        // A fragments: 2 row-groups x 2 images x 4 k-steps (resident, 64 regs)
        uint32_t af[2][2][4][4];
        {
            int kh = (lane >> 4) & 1;
            #pragma unroll
            for (int g = 0; g < 2; g++) {
                int row = g * 128 + wid * 16 + (lane & 15);
                #pragma unroll
                for (int q = 0; q < 2; q++)
                    #pragma unroll
                    for (int ks = 0; ks < 4; ks++) {
                        uint32_t a = su + A_OFF + q * AIMG + row * LDBB + ks * 32 + kh * 16;
                        LDSM_X4(af[g][q][ks][0], af[g][q][ks][1],
                                af[g][q][ks][2], af[g][q][ks][3], a);
                    }
            }
        }

        float best0[2] = {3.4e38f, 3.4e38f}, best1[2] = {3.4e38f, 3.4e38f};
        int   bidx0[2] = {0, 0},             bidx1[2] = {0, 0};

        float* encb = out + ENC_OFF + (size_t)n0 * KCODE;
        float4* enc4 = (float4*)(encb + 2);
        if (tid == 0) *(float2*)encb = make_float2(0.f, 0.f);
        if (tid == 1) *(float2*)(encb + (size_t)BM * KCODE - 2) = make_float2(0.f, 0.f);

        for (int nt = 0; nt < NCHUNK; nt++) {
            CPA_WAIT0();
            __syncthreads();
            if (nt + 1 < NCHUNK) {
                uint32_t d0 = su + B_OFF + ((nt + 1) & 1) * BCHUNKB;
                unsigned long long so = (unsigned long long)(nt + 1) * CHB;
                CPA16(d0 + cpa_dst[0], cpa_src[0] + so);
                CPA16(d0 + cpa_dst[1], cpa_src[1] + so);
                if (has3) CPA16(d0 + cpa_dst[2], cpa_src[2] + so);
                CPA_COMMIT();
            }
            const uint32_t bufo = su + B_OFF + (nt & 1) * BCHUNKB;

            // t-tiles processed sequentially: acc is only 2x4 regs live at once
            #pragma unroll
            for (int t = 0; t < 4; t++) {
                float accA[4] = {0.f, 0.f, 0.f, 0.f};   // group 0
                float accB[4] = {0.f, 0.f, 0.f, 0.f};   // group 1

                #pragma unroll
                for (int kp = 0; kp < 2; kp++) {        // ks pairs {0,1}, {2,3}
                    const int k0 = kp * 2, k1 = kp * 2 + 1;
                    const uint32_t tb = bufo + t * 8 * LDBB + kp * 64 + bofs4;
                    uint32_t bh[4], bl[4];
                    LDSM_X4(bh[0], bh[1], bh[2], bh[3], tb);
                    LDSM_X4(bl[0], bl[1], bl[2], bl[3], tb + CHB);
                    // per-acc order: hh@k0, hl@k0, lh@k0, hh@k1, hl@k1, lh@k1
                    MMA_F16(accA[0],accA[1],accA[2],accA[3],
                            af[0][0][k0][0],af[0][0][k0][1],af[0][0][k0][2],af[0][0][k0][3],
                            bh[0],bh[1]);
                    MMA_F16(accB[0],accB[1],accB[2],accB[3],
                            af[1][0][k0][0],af[1][0][k0][1],af[1][0][k0][2],af[1][0][k0][3],
                            bh[0],bh[1]);
                    MMA_F16(accA[0],accA[1],accA[2],accA[3],
                            af[0][0][k0][0],af[0][0][k0][1],af[0][0][k0][2],af[0][0][k0][3],
                            bl[0],bl[1]);
                    MMA_F16(accB[0],accB[1],accB[2],accB[3],
                            af[1][0][k0][0],af[1][0][k0][1],af[1][0][k0][2],af[1][0][k0][3],
                            bl[0],bl[1]);
                    MMA_F16(accA[0],accA[1],accA[2],accA[3],
                            af[0][1][k0][0],af[0][1][k0][1],af[0][1][k0][2],af[0][1][k0][3],
                            bh[0],bh[1]);
                    MMA_F16(accB[0],accB[1],accB[2],accB[3],
                            af[1][1][k0][0],af[1][1][k0][1],af[1][1][k0][2],af[1][1][k0][3],
                            bh[0],bh[1]);
                    MMA_F16(accA[0],accA[1],accA[2],accA[3],
                            af[0][0][k1][0],af[0][0][k1][1],af[0][0][k1][2],af[0][0][k1][3],
                            bh[2],bh[3]);
                    MMA_F16(accB[0],accB[1],accB[2],accB[3],
                            af[1][0][k1][0],af[1][0][k1][1],af[1][0][k1][2],af[1][0][k1][3],
                            bh[2],bh[3]);
                    MMA_F16(accA[0],accA[1],accA[2],accA[3],
                            af[0][0][k1][0],af[0][0][k1][1],af[0][0][k1][2],af[0][0][k1][3],
                            bl[2],bl[3]);
                    MMA_F16(accB[0],accB[1],accB[2],accB[3],
                            af[1][0][k1][0],af[1][0][k1][1],af[1][0][k1][2],af[1][0][k1][3],
                            bl[2],bl[3]);
                    MMA_F16(accA[0],accA[1],accA[2],accA[3],
                            af[0][1][k1][0],af[0][1][k1][1],af[0][1][k1][2],af[0][1][k1][3],
                            bh[2],bh[3]);
                    MMA_F16(accB[0],accB[1],accB[2],accB[3],
                            af[1][1][k1][0],af[1][1][k1][1],af[1][1][k1][2],af[1][1][k1][3],
                            bh[2],bh[3]);
                }

                // per-t epilogue: d_cmp = he2 - dot/256 (ascending codes, strict <)
                const int ca = nt * CHW + t * 8 + (lane & 3) * 2;   // code pair base
                const float ha = he2s[ca], hb = he2s[ca + 1];
                {   // group 0, rows r0 / r1
                    float da = fmaf(NEG1S, accA[0], ha);
                    float db = fmaf(NEG1S, accA[1], hb);
                    float m = fminf(da, db);
                    if (m < best0[0]) { best0[0] = m; bidx0[0] = (da == m) ? ca : ca + 1; }
                    da = fmaf(NEG1S, accA[2], ha);
                    db = fmaf(NEG1S, accA[3], hb);
                    m = fminf(da, db);
                    if (m < best1[0]) { best1[0] = m; bidx1[0] = (da == m) ? ca : ca + 1; }
                }
                {   // group 1
                    float da = fmaf(NEG1S, accB[0], ha);
                    float db = fmaf(NEG1S, accB[1], hb);
                    float m = fminf(da, db);
                    if (m < best0[1]) { best0[1] = m; bidx0[1] = (da == m) ? ca : ca + 1; }
                    da = fmaf(NEG1S, accB[2], ha);
                    db = fmaf(NEG1S, accB[3], hb);
                    m = fminf(da, db);
                    if (m < best1[1]) { best1[1] = m; bidx1[1] = (da == m) ? ca : ca + 1; }
                }

                // interleaved encodings zero-fill (65535 float4 per block)
                #pragma unroll
                for (int u = 0; u < 2; u++) {
                    int i = (nt * 4 + t) * 512 + u * 256 + tid;
                    if (i < 65535) enc4[i] = make_float4(0.f, 0.f, 0.f, 0.f);
                }
            }
        }

        // cross-lane argmin reduce (4 lanes per row), idx tie-break
        #pragma unroll
        for (int g = 0; g < 2; g++) {
            #pragma unroll
            for (int off = 1; off < 4; off <<= 1) {
                float ob = __shfl_xor_sync(0xffffffffu, best0[g], off);
                int   oi = __shfl_xor_sync(0xffffffffu, bidx0[g], off);
                if (ob < best0[g] || (ob == best0[g] && oi < bidx0[g])) { best0[g] = ob; bidx0[g] = oi; }
                ob = __shfl_xor_sync(0xffffffffu, best1[g], off);
                oi = __shfl_xor_sync(0xffffffffu, bidx1[g], off);
                if (ob < best1[g] || (ob == best1[g] && oi < bidx1[g])) { best1[g] = ob; bidx1[g] = oi; }
            }
            if ((lane & 3) == 0) {
                int r0 = g * 128 + wid * 16 + (lane >> 2);
                rmin[r0] = fmaf(2.f, best0[g], x2s[r0]);         ridx[r0] = bidx0[g];
                rmin[r0 + 8] = fmaf(2.f, best1[g], x2s[r0 + 8]); ridx[r0 + 8] = bidx1[g];
            }
        }
        __syncthreads();

        atomicAdd(&g_counts[ridx[tid]], 1);     // 256 rows, one per thread

        if (tid < 32) {
            double s = 0.0;
            #pragma unroll
            for (int k = 0; k < 8; k++) s += (double)rmin[tid + k * 32];
            #pragma unroll
            for (int o = 16; o > 0; o >>= 1)
                s += __shfl_down_sync(0xffffffffu, s, o);
            if (tid == 0) atomicAdd(&g_loss_sum, s);
        }

        // quantized output (NCHW), coalesced over r
        float* qout = out + Q_OFF;
        #pragma unroll
        for (int i = 0; i < (BM * DIMS) / THREADS; i++) {   // 64
            int idx = tid + i * THREADS;
            int c = idx >> 8;
            int r = idx & 255;
            qout[(size_t)b * 65536 + (size_t)c * 1024 + hw0 + r] =
                cb[(size_t)ridx[r] * DIMS + c];
        }

        encb[(size_t)tid * KCODE + ridx[tid]] = 1.0f;
    }

    // ================= phase 2: last CTA finalizes + resets state =================
    __threadfence();
    if (tid == 0) {
        int d = atomicAdd(&g_done, 1);
        *slast = (d == GRID - 1) ? 1 : 0;
    }
    __syncthreads();
    if (*slast) {
        __threadfence();
        float* red = x2s;               // reuse smem scratch
        float acc = 0.f;
        #pragma unroll
        for (int i = 0; i < 4; i++) {
            int k = tid + i * 256;
            int c = g_counts[k];
            g_counts[k] = 0;
            float p = (float)c * (1.f / 65536.f);
            acc += p * logf(p + 1e-10f);
        }
        #pragma unroll
        for (int o = 16; o > 0; o >>= 1)
            acc += __shfl_down_sync(0xffffffffu, acc, o);
        if (lane == 0) red[wid] = acc;
        __syncthreads();
        if (tid == 0) {
            float s = 0.f;
            #pragma unroll
            for (int w = 0; w < 8; w++) s += red[w];
            out[P_OFF] = expf(-s);
            out[0]     = (float)(1.25 * g_loss_sum / 4194304.0);
            g_loss_sum   = 0.0;
            g_blk        = 0;
            g_done       = 0;
            g_prep_done  = 0;
        }
    }
}

extern "C" void kernel_launch(void* const* d_in, const int* in_sizes, int n_in,
                              void* d_out, int out_size) {
    const float* x  = (const float*)d_in[0];
    const float* cb = (const float*)d_in[1];
    float* out = (float*)d_out;

    cudaFuncSetAttribute(vq_kernel,
                         cudaFuncAttributeMaxDynamicSharedMemorySize, SMEM_BYTES);

    vq_kernel<<<GRID, THREADS, SMEM_BYTES>>>(x, cb, out);
}